// round 3
// baseline (speedup 1.0000x reference)
#include <cuda_runtime.h>
#include <cuda_bf16.h>
#include <math.h>

#define T_STEPS 4096
#define D_IN    512
#define TRACE   64
#define CTX     64
#define OUT_D   512
#define ZDIM    (2*TRACE*CTX)   // 8192
#define LN_EPS  1e-6f

// ---------------- scratch (no cudaMalloc allowed) ----------------
__device__ float g_gated[T_STEPS * TRACE];        // 1 MB
__device__ float g_go   [T_STEPS * OUT_D];        // 8 MB  sigmoid(x@W_go+b)
__device__ float g_skip [T_STEPS * OUT_D];        // 8 MB
__device__ float g_zin  [(size_t)T_STEPS * ZDIM]; // 134 MB
__device__ float g_zm   [T_STEPS * OUT_D];        // 8 MB
__device__ int   g_resets[T_STEPS];               // normalized reset flags
__device__ float g_fs_re[TRACE * CTX];            // final state real
__device__ float g_fs_im[TRACE * CTX];            // final state imag

// ---------------- kernel 0: normalize resets (int32 / float32 / byte bools all -> int 0/1) ----------------
__global__ __launch_bounds__(256) void normalize_resets_kernel(const unsigned char* __restrict__ raw)
{
    const int tid = threadIdx.x;
    const unsigned int* w = (const unsigned int*)raw;

    int f_wide = 0, f_byte = 0;
    for (int i = tid; i < 1024; i += 256) {
        const unsigned int v = w[i];
        if (v & 0xFEFEFEFEu)      f_wide = 1;   // float32 bools (0x3F800000)
        else if (v & 0xFFFFFF00u) f_byte = 1;   // packed 1-byte bools
    }
    f_wide = __syncthreads_or(f_wide);
    f_byte = __syncthreads_or(f_byte);
    const int one_byte = (!f_wide && f_byte);

    if (one_byte) {
        for (int t = tid; t < T_STEPS; t += 256) g_resets[t] = (raw[t] != 0);
    } else {
        for (int t = tid; t < T_STEPS; t += 256) g_resets[t] = (w[t] != 0u);
    }
}

// ---------------- kernel 1: gated = sigmoid(x@W_gi+b_gi) * (x@W_pre+b_pre) ----------------
__global__ __launch_bounds__(64) void gated_kernel(
    const float* __restrict__ x,
    const float* __restrict__ W_gi, const float* __restrict__ b_gi,
    const float* __restrict__ W_pre, const float* __restrict__ b_pre,
    float* __restrict__ gated)
{
    __shared__ float xs[8][D_IN];
    const int t0 = blockIdx.x * 8;
    const int i  = threadIdx.x;

    for (int idx = i; idx < 8 * D_IN; idx += 64)
        xs[idx >> 9][idx & 511] = x[(size_t)t0 * D_IN + idx];
    __syncthreads();

    float agi[8], apre[8];
    const float bg = b_gi[i], bp = b_pre[i];
#pragma unroll
    for (int tt = 0; tt < 8; ++tt) { agi[tt] = bg; apre[tt] = bp; }

#pragma unroll 4
    for (int k = 0; k < D_IN; ++k) {
        const float wg = W_gi[k * TRACE + i];
        const float wp = W_pre[k * TRACE + i];
#pragma unroll
        for (int tt = 0; tt < 8; ++tt) {
            const float xv = xs[tt][k];
            agi[tt]  = fmaf(xv, wg, agi[tt]);
            apre[tt] = fmaf(xv, wp, apre[tt]);
        }
    }
#pragma unroll
    for (int tt = 0; tt < 8; ++tt) {
        const float gate = 1.f / (1.f + expf(-agi[tt]));
        gated[(t0 + tt) * TRACE + i] = gate * apre[tt];
    }
}

// ---------------- kernel 2: fp32 SGEMM  C = A[MxK]@B[KxN] + bias (mode 1: sigmoid) ----------------
__global__ __launch_bounds__(256) void gemm128(
    const float* __restrict__ A, const float* __restrict__ B,
    const float* __restrict__ bias, float* __restrict__ C,
    int M, int N, int K, int mode)
{
    __shared__ float As[16][128];
    __shared__ float Bs[16][128];

    const int bm = blockIdx.y, bn = blockIdx.x;
    const int tid = threadIdx.x;
    const int tx = tid & 15;
    const int ty = tid >> 4;

    const float* Ablk = A + (size_t)bm * 128 * K;
    const float* Bblk = B + bn * 128;

    float acc[8][8];
#pragma unroll
    for (int m = 0; m < 8; ++m)
#pragma unroll
        for (int n = 0; n < 8; ++n) acc[m][n] = 0.f;

    for (int k0 = 0; k0 < K; k0 += 16) {
#pragma unroll
        for (int l = 0; l < 2; ++l) {
            const int idx = tid + l * 256;
            const int row = idx >> 2;
            const int k4  = (idx & 3) << 2;
            const float4 v = *(const float4*)(Ablk + (size_t)row * K + k0 + k4);
            As[k4 + 0][row] = v.x;
            As[k4 + 1][row] = v.y;
            As[k4 + 2][row] = v.z;
            As[k4 + 3][row] = v.w;
        }
#pragma unroll
        for (int l = 0; l < 2; ++l) {
            const int idx  = tid + l * 256;
            const int krow = idx >> 5;
            const int c4   = (idx & 31) << 2;
            *(float4*)&Bs[krow][c4] = *(const float4*)(Bblk + (size_t)(k0 + krow) * N + c4);
        }
        __syncthreads();

#pragma unroll
        for (int kk = 0; kk < 16; ++kk) {
            float aF[8], bF[8];
            *(float4*)&aF[0] = *(const float4*)&As[kk][ty * 8];
            *(float4*)&aF[4] = *(const float4*)&As[kk][ty * 8 + 4];
            *(float4*)&bF[0] = *(const float4*)&Bs[kk][tx * 8];
            *(float4*)&bF[4] = *(const float4*)&Bs[kk][tx * 8 + 4];
#pragma unroll
            for (int m = 0; m < 8; ++m)
#pragma unroll
                for (int n = 0; n < 8; ++n)
                    acc[m][n] = fmaf(aF[m], bF[n], acc[m][n]);
        }
        __syncthreads();
    }

    const int row0 = bm * 128 + ty * 8;
    const int col0 = bn * 128 + tx * 8;
    float bia[8];
#pragma unroll
    for (int n = 0; n < 8; ++n) bia[n] = bias[col0 + n];

#pragma unroll
    for (int m = 0; m < 8; ++m) {
        float v[8];
#pragma unroll
        for (int n = 0; n < 8; ++n) {
            float val = acc[m][n] + bia[n];
            if (mode == 1) val = 1.f / (1.f + expf(-val));
            v[n] = val;
        }
        *(float4*)(C + (size_t)(row0 + m) * N + col0)     = make_float4(v[0], v[1], v[2], v[3]);
        *(float4*)(C + (size_t)(row0 + m) * N + col0 + 4) = make_float4(v[4], v[5], v[6], v[7]);
    }
}

// ---------------- kernel 3: segmented complex recurrence ----------------
__global__ __launch_bounds__(64) void recurrence_kernel(
    const float* __restrict__ gated,
    const float* __restrict__ state_re, const float* __restrict__ state_im,
    const float* __restrict__ a, const float* __restrict__ b,
    float* __restrict__ z_in)
{
    const int i = blockIdx.x;
    const int j = threadIdx.x;

    const float decay = expf(-fabsf(a[i]));
    const float wr = decay * cosf(b[j]);
    const float wi = decay * sinf(b[j]);

    float re = state_re[i * CTX + j];
    float im = state_im[i * CTX + j];

    float* zrow_re = z_in + i * 128 + j;
    float* zrow_im = z_in + i * 128 + 64 + j;
    const float* gcol = gated + i;

#pragma unroll 4
    for (int t = 0; t < T_STEPS; ++t) {
        const float g = __ldg(gcol + (size_t)t * TRACE);
        if (g_resets[t]) { re = 0.f; im = 0.f; }
        const float nre = fmaf(re, wr, fmaf(-im, wi, g));
        const float nim = fmaf(re, wi, im * wr);
        re = nre; im = nim;
        zrow_re[(size_t)t * ZDIM] = re;
        zrow_im[(size_t)t * ZDIM] = im;
    }

    g_fs_re[i * CTX + j] = re;
    g_fs_im[i * CTX + j] = im;
}

// ---------------- kernel 3b: materialize final_state in the requested layout ----------------
// mode 0: real-only (4096 floats)          [astype(float32) discards imag]
// mode 1: planar  [re(4096) | im(4096)]
// mode 2: interleaved [re,im]*4096
__global__ __launch_bounds__(256) void finalize_state_kernel(float* __restrict__ dst, int mode)
{
    const int k = blockIdx.x * 256 + threadIdx.x;
    if (k >= TRACE * CTX) return;
    const float re = g_fs_re[k];
    const float im = g_fs_im[k];
    if (mode == 0) {
        dst[k] = re;
    } else if (mode == 1) {
        dst[k] = re;
        dst[TRACE * CTX + k] = im;
    } else {
        dst[2 * k]     = re;
        dst[2 * k + 1] = im;
    }
}

// ---------------- kernel 4: epilogue ----------------
__global__ __launch_bounds__(256) void epilogue_kernel(
    const float* __restrict__ zm, const float* __restrict__ go,
    const float* __restrict__ skp, float* __restrict__ out)
{
    const int t = blockIdx.x;
    const int tid = threadIdx.x;
    __shared__ float s_sum[8], s_sq[8];

    float v[2], gg[2], sk[2];
    float sum = 0.f, sq = 0.f;
#pragma unroll
    for (int l = 0; l < 2; ++l) {
        const int o = tid + l * 256;
        const float z = zm[(size_t)t * OUT_D + o];
        const float g = go[(size_t)t * OUT_D + o];
        v[l]  = z * g;
        gg[l] = g;
        sk[l] = skp[(size_t)t * OUT_D + o];
        sum += v[l];
        sq  += v[l] * v[l];
    }
#pragma unroll
    for (int off = 16; off > 0; off >>= 1) {
        sum += __shfl_xor_sync(0xFFFFFFFF, sum, off);
        sq  += __shfl_xor_sync(0xFFFFFFFF, sq,  off);
    }
    const int wid = tid >> 5, lid = tid & 31;
    if (lid == 0) { s_sum[wid] = sum; s_sq[wid] = sq; }
    __syncthreads();
    if (wid == 0) {
        float a0 = (lid < 8) ? s_sum[lid] : 0.f;
        float b0 = (lid < 8) ? s_sq[lid]  : 0.f;
#pragma unroll
        for (int off = 4; off > 0; off >>= 1) {
            a0 += __shfl_xor_sync(0xFFFFFFFF, a0, off);
            b0 += __shfl_xor_sync(0xFFFFFFFF, b0, off);
        }
        if (lid == 0) { s_sum[0] = a0; s_sq[0] = b0; }
    }
    __syncthreads();
    const float mu  = s_sum[0] * (1.f / OUT_D);
    const float var = s_sq[0] * (1.f / OUT_D) - mu * mu;
    const float inv = rsqrtf(var + LN_EPS);
#pragma unroll
    for (int l = 0; l < 2; ++l) {
        const int o = tid + l * 256;
        out[(size_t)t * OUT_D + o] = (v[l] - mu) * inv + sk[l] * (1.f - gg[l]);
    }
}

// ---------------- launch ----------------
extern "C" void kernel_launch(void* const* d_in, const int* in_sizes, int n_in,
                              void* d_out, int out_size)
{
    const float* x        = (const float*)d_in[0];
    const unsigned char* resets_raw = (const unsigned char*)d_in[1];
    const float* state_re = (const float*)d_in[2];
    const float* state_im = (const float*)d_in[3];
    const float* a        = (const float*)d_in[4];
    const float* b        = (const float*)d_in[5];
    const float* W_pre    = (const float*)d_in[6];
    const float* b_pre    = (const float*)d_in[7];
    const float* W_gi     = (const float*)d_in[8];
    const float* b_gi     = (const float*)d_in[9];
    const float* W_go     = (const float*)d_in[10];
    const float* b_go     = (const float*)d_in[11];
    const float* W_skip   = (const float*)d_in[12];
    const float* b_skip   = (const float*)d_in[13];
    const float* W_mix    = (const float*)d_in[14];
    const float* b_mix    = (const float*)d_in[15];

    // Output layout dispatch on out_size:
    //   2101248 = 4096 + 4096*512        -> final_state stored real-only (astype(f32))
    //   2105344 = 8192 + 4096*512        -> 8192 floats of state; planar [re|im]
    //   otherwise                        -> interleaved fallback
    int fs_mode;
    int seq_off;
    if (out_size == TRACE * CTX + T_STEPS * OUT_D)            { fs_mode = 0; seq_off = TRACE * CTX; }
    else if (out_size == 2 * TRACE * CTX + T_STEPS * OUT_D)   { fs_mode = 1; seq_off = 2 * TRACE * CTX; }
    else                                                      { fs_mode = 2; seq_off = 2 * TRACE * CTX; }

    float* out_f   = (float*)d_out;
    float* fs_out  = out_f;
    float* seq_out = out_f + seq_off;

    float *p_gated, *p_go, *p_skip, *p_zin, *p_zm;
    cudaGetSymbolAddress((void**)&p_gated, g_gated);
    cudaGetSymbolAddress((void**)&p_go,    g_go);
    cudaGetSymbolAddress((void**)&p_skip,  g_skip);
    cudaGetSymbolAddress((void**)&p_zin,   g_zin);
    cudaGetSymbolAddress((void**)&p_zm,    g_zm);

    normalize_resets_kernel<<<1, 256>>>(resets_raw);

    gated_kernel<<<T_STEPS / 8, 64>>>(x, W_gi, b_gi, W_pre, b_pre, p_gated);

    gemm128<<<dim3(OUT_D / 128, T_STEPS / 128), 256>>>(x, W_go,   b_go,   p_go,   T_STEPS, OUT_D, D_IN, 1);
    gemm128<<<dim3(OUT_D / 128, T_STEPS / 128), 256>>>(x, W_skip, b_skip, p_skip, T_STEPS, OUT_D, D_IN, 0);

    recurrence_kernel<<<TRACE, CTX>>>(p_gated, state_re, state_im, a, b, p_zin);
    finalize_state_kernel<<<(TRACE * CTX + 255) / 256, 256>>>(fs_out, fs_mode);

    gemm128<<<dim3(OUT_D / 128, T_STEPS / 128), 256>>>(p_zin, W_mix, b_mix, p_zm, T_STEPS, OUT_D, ZDIM, 0);

    epilogue_kernel<<<T_STEPS, 256>>>(p_zm, p_go, p_skip, seq_out);
}

// round 4
// speedup vs baseline: 1.0002x; 1.0002x over previous
#include <cuda_runtime.h>
#include <cuda_bf16.h>
#include <math.h>

#define T_STEPS 4096
#define D_IN    512
#define TRACE   64
#define CTX     64
#define OUT_D   512
#define ZDIM    (2*TRACE*CTX)   // 8192
#define LN_EPS  1e-6f

// ---------------- scratch (no cudaMalloc allowed) ----------------
__device__ float g_gated[T_STEPS * TRACE];        // 1 MB
__device__ float g_go   [T_STEPS * OUT_D];        // 8 MB  sigmoid(x@W_go+b)
__device__ float g_skip [T_STEPS * OUT_D];        // 8 MB
__device__ float g_zin  [(size_t)T_STEPS * ZDIM]; // 134 MB
__device__ float g_zm   [T_STEPS * OUT_D];        // 8 MB
__device__ int   g_resets[T_STEPS];               // normalized reset flags
__device__ float g_fs_re[TRACE * CTX];            // final state real
__device__ float g_fs_im[TRACE * CTX];            // final state imag

// ---------------- kernel 0: normalize resets (int32 / float32 / byte bools all -> int 0/1) ----------------
__global__ __launch_bounds__(256) void normalize_resets_kernel(const unsigned char* __restrict__ raw)
{
    const int tid = threadIdx.x;
    const unsigned int* w = (const unsigned int*)raw;

    int f_wide = 0, f_byte = 0;
    for (int i = tid; i < 1024; i += 256) {
        const unsigned int v = w[i];
        if (v & 0xFEFEFEFEu)      f_wide = 1;   // float32 bools (0x3F800000)
        else if (v & 0xFFFFFF00u) f_byte = 1;   // packed 1-byte bools
    }
    f_wide = __syncthreads_or(f_wide);
    f_byte = __syncthreads_or(f_byte);
    const int one_byte = (!f_wide && f_byte);

    if (one_byte) {
        for (int t = tid; t < T_STEPS; t += 256) g_resets[t] = (raw[t] != 0);
    } else {
        for (int t = tid; t < T_STEPS; t += 256) g_resets[t] = (w[t] != 0u);
    }
}

// ---------------- kernel 1: gated = sigmoid(x@W_gi+b_gi) * (x@W_pre+b_pre) ----------------
__global__ __launch_bounds__(64) void gated_kernel(
    const float* __restrict__ x,
    const float* __restrict__ W_gi, const float* __restrict__ b_gi,
    const float* __restrict__ W_pre, const float* __restrict__ b_pre,
    float* __restrict__ gated)
{
    __shared__ float xs[8][D_IN];
    const int t0 = blockIdx.x * 8;
    const int i  = threadIdx.x;

    for (int idx = i; idx < 8 * D_IN; idx += 64)
        xs[idx >> 9][idx & 511] = x[(size_t)t0 * D_IN + idx];
    __syncthreads();

    float agi[8], apre[8];
    const float bg = b_gi[i], bp = b_pre[i];
#pragma unroll
    for (int tt = 0; tt < 8; ++tt) { agi[tt] = bg; apre[tt] = bp; }

#pragma unroll 4
    for (int k = 0; k < D_IN; ++k) {
        const float wg = W_gi[k * TRACE + i];
        const float wp = W_pre[k * TRACE + i];
#pragma unroll
        for (int tt = 0; tt < 8; ++tt) {
            const float xv = xs[tt][k];
            agi[tt]  = fmaf(xv, wg, agi[tt]);
            apre[tt] = fmaf(xv, wp, apre[tt]);
        }
    }
#pragma unroll
    for (int tt = 0; tt < 8; ++tt) {
        const float gate = 1.f / (1.f + expf(-agi[tt]));
        gated[(t0 + tt) * TRACE + i] = gate * apre[tt];
    }
}

// ---------------- kernel 2: fp32 SGEMM  C = A[MxK]@B[KxN] + bias (mode 1: sigmoid) ----------------
__global__ __launch_bounds__(256) void gemm128(
    const float* __restrict__ A, const float* __restrict__ B,
    const float* __restrict__ bias, float* __restrict__ C,
    int M, int N, int K, int mode)
{
    __shared__ float As[16][128];
    __shared__ float Bs[16][128];

    const int bm = blockIdx.y, bn = blockIdx.x;
    const int tid = threadIdx.x;
    const int tx = tid & 15;
    const int ty = tid >> 4;

    const float* Ablk = A + (size_t)bm * 128 * K;
    const float* Bblk = B + bn * 128;

    float acc[8][8];
#pragma unroll
    for (int m = 0; m < 8; ++m)
#pragma unroll
        for (int n = 0; n < 8; ++n) acc[m][n] = 0.f;

    for (int k0 = 0; k0 < K; k0 += 16) {
#pragma unroll
        for (int l = 0; l < 2; ++l) {
            const int idx = tid + l * 256;
            const int row = idx >> 2;
            const int k4  = (idx & 3) << 2;
            const float4 v = *(const float4*)(Ablk + (size_t)row * K + k0 + k4);
            As[k4 + 0][row] = v.x;
            As[k4 + 1][row] = v.y;
            As[k4 + 2][row] = v.z;
            As[k4 + 3][row] = v.w;
        }
#pragma unroll
        for (int l = 0; l < 2; ++l) {
            const int idx  = tid + l * 256;
            const int krow = idx >> 5;
            const int c4   = (idx & 31) << 2;
            *(float4*)&Bs[krow][c4] = *(const float4*)(Bblk + (size_t)(k0 + krow) * N + c4);
        }
        __syncthreads();

#pragma unroll
        for (int kk = 0; kk < 16; ++kk) {
            float aF[8], bF[8];
            *(float4*)&aF[0] = *(const float4*)&As[kk][ty * 8];
            *(float4*)&aF[4] = *(const float4*)&As[kk][ty * 8 + 4];
            *(float4*)&bF[0] = *(const float4*)&Bs[kk][tx * 8];
            *(float4*)&bF[4] = *(const float4*)&Bs[kk][tx * 8 + 4];
#pragma unroll
            for (int m = 0; m < 8; ++m)
#pragma unroll
                for (int n = 0; n < 8; ++n)
                    acc[m][n] = fmaf(aF[m], bF[n], acc[m][n]);
        }
        __syncthreads();
    }

    const int row0 = bm * 128 + ty * 8;
    const int col0 = bn * 128 + tx * 8;
    float bia[8];
#pragma unroll
    for (int n = 0; n < 8; ++n) bia[n] = bias[col0 + n];

#pragma unroll
    for (int m = 0; m < 8; ++m) {
        float v[8];
#pragma unroll
        for (int n = 0; n < 8; ++n) {
            float val = acc[m][n] + bia[n];
            if (mode == 1) val = 1.f / (1.f + expf(-val));
            v[n] = val;
        }
        *(float4*)(C + (size_t)(row0 + m) * N + col0)     = make_float4(v[0], v[1], v[2], v[3]);
        *(float4*)(C + (size_t)(row0 + m) * N + col0 + 4) = make_float4(v[4], v[5], v[6], v[7]);
    }
}

// ---------------- kernel 3: segmented complex recurrence ----------------
__global__ __launch_bounds__(64) void recurrence_kernel(
    const float* __restrict__ gated,
    const float* __restrict__ state_re, const float* __restrict__ state_im,
    const float* __restrict__ a, const float* __restrict__ b,
    float* __restrict__ z_in)
{
    const int i = blockIdx.x;
    const int j = threadIdx.x;

    const float decay = expf(-fabsf(a[i]));
    const float wr = decay * cosf(b[j]);
    const float wi = decay * sinf(b[j]);

    float re = state_re[i * CTX + j];
    float im = state_im[i * CTX + j];

    float* zrow_re = z_in + i * 128 + j;
    float* zrow_im = z_in + i * 128 + 64 + j;
    const float* gcol = gated + i;

#pragma unroll 4
    for (int t = 0; t < T_STEPS; ++t) {
        const float g = __ldg(gcol + (size_t)t * TRACE);
        if (g_resets[t]) { re = 0.f; im = 0.f; }
        const float nre = fmaf(re, wr, fmaf(-im, wi, g));
        const float nim = fmaf(re, wi, im * wr);
        re = nre; im = nim;
        zrow_re[(size_t)t * ZDIM] = re;
        zrow_im[(size_t)t * ZDIM] = im;
    }

    g_fs_re[i * CTX + j] = re;
    g_fs_im[i * CTX + j] = im;
}

// ---------------- kernel 3b: materialize final_state in the requested layout ----------------
// mode 0: real-only (4096 floats)          [astype(float32) discards imag]
// mode 1: planar  [re(4096) | im(4096)]
// mode 2: interleaved [re,im]*4096
__global__ __launch_bounds__(256) void finalize_state_kernel(float* __restrict__ dst, int mode)
{
    const int k = blockIdx.x * 256 + threadIdx.x;
    if (k >= TRACE * CTX) return;
    const float re = g_fs_re[k];
    const float im = g_fs_im[k];
    if (mode == 0) {
        dst[k] = re;
    } else if (mode == 1) {
        dst[k] = re;
        dst[TRACE * CTX + k] = im;
    } else {
        dst[2 * k]     = re;
        dst[2 * k + 1] = im;
    }
}

// ---------------- kernel 4: epilogue ----------------
__global__ __launch_bounds__(256) void epilogue_kernel(
    const float* __restrict__ zm, const float* __restrict__ go,
    const float* __restrict__ skp, float* __restrict__ out)
{
    const int t = blockIdx.x;
    const int tid = threadIdx.x;
    __shared__ float s_sum[8], s_sq[8];

    float v[2], gg[2], sk[2];
    float sum = 0.f, sq = 0.f;
#pragma unroll
    for (int l = 0; l < 2; ++l) {
        const int o = tid + l * 256;
        const float z = zm[(size_t)t * OUT_D + o];
        const float g = go[(size_t)t * OUT_D + o];
        v[l]  = z * g;
        gg[l] = g;
        sk[l] = skp[(size_t)t * OUT_D + o];
        sum += v[l];
        sq  += v[l] * v[l];
    }
#pragma unroll
    for (int off = 16; off > 0; off >>= 1) {
        sum += __shfl_xor_sync(0xFFFFFFFF, sum, off);
        sq  += __shfl_xor_sync(0xFFFFFFFF, sq,  off);
    }
    const int wid = tid >> 5, lid = tid & 31;
    if (lid == 0) { s_sum[wid] = sum; s_sq[wid] = sq; }
    __syncthreads();
    if (wid == 0) {
        float a0 = (lid < 8) ? s_sum[lid] : 0.f;
        float b0 = (lid < 8) ? s_sq[lid]  : 0.f;
#pragma unroll
        for (int off = 4; off > 0; off >>= 1) {
            a0 += __shfl_xor_sync(0xFFFFFFFF, a0, off);
            b0 += __shfl_xor_sync(0xFFFFFFFF, b0, off);
        }
        if (lid == 0) { s_sum[0] = a0; s_sq[0] = b0; }
    }
    __syncthreads();
    const float mu  = s_sum[0] * (1.f / OUT_D);
    const float var = s_sq[0] * (1.f / OUT_D) - mu * mu;
    const float inv = rsqrtf(var + LN_EPS);
#pragma unroll
    for (int l = 0; l < 2; ++l) {
        const int o = tid + l * 256;
        out[(size_t)t * OUT_D + o] = (v[l] - mu) * inv + sk[l] * (1.f - gg[l]);
    }
}

// ---------------- launch ----------------
extern "C" void kernel_launch(void* const* d_in, const int* in_sizes, int n_in,
                              void* d_out, int out_size)
{
    const float* x        = (const float*)d_in[0];
    const unsigned char* resets_raw = (const unsigned char*)d_in[1];
    const float* state_re = (const float*)d_in[2];
    const float* state_im = (const float*)d_in[3];
    const float* a        = (const float*)d_in[4];
    const float* b        = (const float*)d_in[5];
    const float* W_pre    = (const float*)d_in[6];
    const float* b_pre    = (const float*)d_in[7];
    const float* W_gi     = (const float*)d_in[8];
    const float* b_gi     = (const float*)d_in[9];
    const float* W_go     = (const float*)d_in[10];
    const float* b_go     = (const float*)d_in[11];
    const float* W_skip   = (const float*)d_in[12];
    const float* b_skip   = (const float*)d_in[13];
    const float* W_mix    = (const float*)d_in[14];
    const float* b_mix    = (const float*)d_in[15];

    // Output layout dispatch on out_size:
    //   2101248 = 4096 + 4096*512        -> final_state stored real-only (astype(f32))
    //   2105344 = 8192 + 4096*512        -> 8192 floats of state; planar [re|im]
    //   otherwise                        -> interleaved fallback
    int fs_mode;
    int seq_off;
    if (out_size == TRACE * CTX + T_STEPS * OUT_D)            { fs_mode = 0; seq_off = TRACE * CTX; }
    else if (out_size == 2 * TRACE * CTX + T_STEPS * OUT_D)   { fs_mode = 1; seq_off = 2 * TRACE * CTX; }
    else                                                      { fs_mode = 2; seq_off = 2 * TRACE * CTX; }

    float* out_f   = (float*)d_out;
    float* fs_out  = out_f;
    float* seq_out = out_f + seq_off;

    float *p_gated, *p_go, *p_skip, *p_zin, *p_zm;
    cudaGetSymbolAddress((void**)&p_gated, g_gated);
    cudaGetSymbolAddress((void**)&p_go,    g_go);
    cudaGetSymbolAddress((void**)&p_skip,  g_skip);
    cudaGetSymbolAddress((void**)&p_zin,   g_zin);
    cudaGetSymbolAddress((void**)&p_zm,    g_zm);

    normalize_resets_kernel<<<1, 256>>>(resets_raw);

    gated_kernel<<<T_STEPS / 8, 64>>>(x, W_gi, b_gi, W_pre, b_pre, p_gated);

    gemm128<<<dim3(OUT_D / 128, T_STEPS / 128), 256>>>(x, W_go,   b_go,   p_go,   T_STEPS, OUT_D, D_IN, 1);
    gemm128<<<dim3(OUT_D / 128, T_STEPS / 128), 256>>>(x, W_skip, b_skip, p_skip, T_STEPS, OUT_D, D_IN, 0);

    recurrence_kernel<<<TRACE, CTX>>>(p_gated, state_re, state_im, a, b, p_zin);
    finalize_state_kernel<<<(TRACE * CTX + 255) / 256, 256>>>(fs_out, fs_mode);

    gemm128<<<dim3(OUT_D / 128, T_STEPS / 128), 256>>>(p_zin, W_mix, b_mix, p_zm, T_STEPS, OUT_D, ZDIM, 0);

    epilogue_kernel<<<T_STEPS, 256>>>(p_zm, p_go, p_skip, seq_out);
}

// round 5
// speedup vs baseline: 1.0663x; 1.0662x over previous
#include <cuda_runtime.h>
#include <cuda_bf16.h>
#include <math.h>

#define T_STEPS 4096
#define D_IN    512
#define TRACE   64
#define CTX     64
#define OUT_D   512
#define ZDIM    (2*TRACE*CTX)   // 8192
#define LN_EPS  1e-6f

// ---------------- scratch (no cudaMalloc allowed) ----------------
__device__ float g_gated[T_STEPS * TRACE];        // 1 MB
__device__ float g_go   [T_STEPS * OUT_D];        // 8 MB  sigmoid(x@W_go+b)
__device__ float g_skip [T_STEPS * OUT_D];        // 8 MB
__device__ float g_zin  [(size_t)T_STEPS * ZDIM]; // 134 MB
__device__ float g_zm   [T_STEPS * OUT_D];        // 8 MB
__device__ int   g_resets[T_STEPS];               // normalized reset flags
__device__ float g_fs_re[TRACE * CTX];            // final state real
__device__ float g_fs_im[TRACE * CTX];            // final state imag

// ---------------- kernel 0: normalize resets (int32 / float32 / byte bools all -> int 0/1) ----------------
__global__ __launch_bounds__(256) void normalize_resets_kernel(const unsigned char* __restrict__ raw)
{
    const int tid = threadIdx.x;
    const unsigned int* w = (const unsigned int*)raw;

    int f_wide = 0, f_byte = 0;
    for (int i = tid; i < 1024; i += 256) {
        const unsigned int v = w[i];
        if (v & 0xFEFEFEFEu)      f_wide = 1;   // float32 bools (0x3F800000)
        else if (v & 0xFFFFFF00u) f_byte = 1;   // packed 1-byte bools
    }
    f_wide = __syncthreads_or(f_wide);
    f_byte = __syncthreads_or(f_byte);
    const int one_byte = (!f_wide && f_byte);

    if (one_byte) {
        for (int t = tid; t < T_STEPS; t += 256) g_resets[t] = (raw[t] != 0);
    } else {
        for (int t = tid; t < T_STEPS; t += 256) g_resets[t] = (w[t] != 0u);
    }
}

// ---------------- kernel 1: gated = sigmoid(x@W_gi+b_gi) * (x@W_pre+b_pre) ----------------
__global__ __launch_bounds__(64) void gated_kernel(
    const float* __restrict__ x,
    const float* __restrict__ W_gi, const float* __restrict__ b_gi,
    const float* __restrict__ W_pre, const float* __restrict__ b_pre,
    float* __restrict__ gated)
{
    __shared__ float xs[8][D_IN];
    const int t0 = blockIdx.x * 8;
    const int i  = threadIdx.x;

    for (int idx = i; idx < 8 * D_IN; idx += 64)
        xs[idx >> 9][idx & 511] = x[(size_t)t0 * D_IN + idx];
    __syncthreads();

    float agi[8], apre[8];
    const float bg = b_gi[i], bp = b_pre[i];
#pragma unroll
    for (int tt = 0; tt < 8; ++tt) { agi[tt] = bg; apre[tt] = bp; }

#pragma unroll 4
    for (int k = 0; k < D_IN; ++k) {
        const float wg = W_gi[k * TRACE + i];
        const float wp = W_pre[k * TRACE + i];
#pragma unroll
        for (int tt = 0; tt < 8; ++tt) {
            const float xv = xs[tt][k];
            agi[tt]  = fmaf(xv, wg, agi[tt]);
            apre[tt] = fmaf(xv, wp, apre[tt]);
        }
    }
#pragma unroll
    for (int tt = 0; tt < 8; ++tt) {
        const float gate = 1.f / (1.f + expf(-agi[tt]));
        gated[(t0 + tt) * TRACE + i] = gate * apre[tt];
    }
}

// ---------------- kernel 2: fp32 SGEMM  C = A[MxK]@B[KxN] + bias (mode 1: sigmoid) ----------------
__global__ __launch_bounds__(256) void gemm128(
    const float* __restrict__ A, const float* __restrict__ B,
    const float* __restrict__ bias, float* __restrict__ C,
    int M, int N, int K, int mode)
{
    __shared__ float As[16][128];
    __shared__ float Bs[16][128];

    const int bm = blockIdx.y, bn = blockIdx.x;
    const int tid = threadIdx.x;
    const int tx = tid & 15;
    const int ty = tid >> 4;

    const float* Ablk = A + (size_t)bm * 128 * K;
    const float* Bblk = B + bn * 128;

    float acc[8][8];
#pragma unroll
    for (int m = 0; m < 8; ++m)
#pragma unroll
        for (int n = 0; n < 8; ++n) acc[m][n] = 0.f;

    for (int k0 = 0; k0 < K; k0 += 16) {
#pragma unroll
        for (int l = 0; l < 2; ++l) {
            const int idx = tid + l * 256;
            const int row = idx >> 2;
            const int k4  = (idx & 3) << 2;
            const float4 v = *(const float4*)(Ablk + (size_t)row * K + k0 + k4);
            As[k4 + 0][row] = v.x;
            As[k4 + 1][row] = v.y;
            As[k4 + 2][row] = v.z;
            As[k4 + 3][row] = v.w;
        }
#pragma unroll
        for (int l = 0; l < 2; ++l) {
            const int idx  = tid + l * 256;
            const int krow = idx >> 5;
            const int c4   = (idx & 31) << 2;
            *(float4*)&Bs[krow][c4] = *(const float4*)(Bblk + (size_t)(k0 + krow) * N + c4);
        }
        __syncthreads();

#pragma unroll
        for (int kk = 0; kk < 16; ++kk) {
            float aF[8], bF[8];
            *(float4*)&aF[0] = *(const float4*)&As[kk][ty * 8];
            *(float4*)&aF[4] = *(const float4*)&As[kk][ty * 8 + 4];
            *(float4*)&bF[0] = *(const float4*)&Bs[kk][tx * 8];
            *(float4*)&bF[4] = *(const float4*)&Bs[kk][tx * 8 + 4];
#pragma unroll
            for (int m = 0; m < 8; ++m)
#pragma unroll
                for (int n = 0; n < 8; ++n)
                    acc[m][n] = fmaf(aF[m], bF[n], acc[m][n]);
        }
        __syncthreads();
    }

    const int row0 = bm * 128 + ty * 8;
    const int col0 = bn * 128 + tx * 8;
    float bia[8];
#pragma unroll
    for (int n = 0; n < 8; ++n) bia[n] = bias[col0 + n];

#pragma unroll
    for (int m = 0; m < 8; ++m) {
        float v[8];
#pragma unroll
        for (int n = 0; n < 8; ++n) {
            float val = acc[m][n] + bia[n];
            if (mode == 1) val = 1.f / (1.f + expf(-val));
            v[n] = val;
        }
        *(float4*)(C + (size_t)(row0 + m) * N + col0)     = make_float4(v[0], v[1], v[2], v[3]);
        *(float4*)(C + (size_t)(row0 + m) * N + col0 + 4) = make_float4(v[4], v[5], v[6], v[7]);
    }
}

// ---------------- kernel 3: segmented complex recurrence ----------------
__global__ __launch_bounds__(64) void recurrence_kernel(
    const float* __restrict__ gated,
    const float* __restrict__ state_re, const float* __restrict__ state_im,
    const float* __restrict__ a, const float* __restrict__ b,
    float* __restrict__ z_in)
{
    const int i = blockIdx.x;
    const int j = threadIdx.x;

    const float decay = expf(-fabsf(a[i]));
    const float wr = decay * cosf(b[j]);
    const float wi = decay * sinf(b[j]);

    float re = state_re[i * CTX + j];
    float im = state_im[i * CTX + j];

    float* zrow_re = z_in + i * 128 + j;
    float* zrow_im = z_in + i * 128 + 64 + j;
    const float* gcol = gated + i;

#pragma unroll 4
    for (int t = 0; t < T_STEPS; ++t) {
        const float g = __ldg(gcol + (size_t)t * TRACE);
        if (g_resets[t]) { re = 0.f; im = 0.f; }
        const float nre = fmaf(re, wr, fmaf(-im, wi, g));
        const float nim = fmaf(re, wi, im * wr);
        re = nre; im = nim;
        zrow_re[(size_t)t * ZDIM] = re;
        zrow_im[(size_t)t * ZDIM] = im;
    }

    g_fs_re[i * CTX + j] = re;
    g_fs_im[i * CTX + j] = im;
}

// ---------------- kernel 3b: materialize final_state in the requested layout ----------------
// mode 0: real-only (4096 floats)          [astype(float32) discards imag]
// mode 1: planar  [re(4096) | im(4096)]
// mode 2: interleaved [re,im]*4096
__global__ __launch_bounds__(256) void finalize_state_kernel(float* __restrict__ dst, int mode)
{
    const int k = blockIdx.x * 256 + threadIdx.x;
    if (k >= TRACE * CTX) return;
    const float re = g_fs_re[k];
    const float im = g_fs_im[k];
    if (mode == 0) {
        dst[k] = re;
    } else if (mode == 1) {
        dst[k] = re;
        dst[TRACE * CTX + k] = im;
    } else {
        dst[2 * k]     = re;
        dst[2 * k + 1] = im;
    }
}

// ---------------- kernel 4: epilogue ----------------
__global__ __launch_bounds__(256) void epilogue_kernel(
    const float* __restrict__ zm, const float* __restrict__ go,
    const float* __restrict__ skp, float* __restrict__ out)
{
    const int t = blockIdx.x;
    const int tid = threadIdx.x;
    __shared__ float s_sum[8], s_sq[8];

    float v[2], gg[2], sk[2];
    float sum = 0.f, sq = 0.f;
#pragma unroll
    for (int l = 0; l < 2; ++l) {
        const int o = tid + l * 256;
        const float z = zm[(size_t)t * OUT_D + o];
        const float g = go[(size_t)t * OUT_D + o];
        v[l]  = z * g;
        gg[l] = g;
        sk[l] = skp[(size_t)t * OUT_D + o];
        sum += v[l];
        sq  += v[l] * v[l];
    }
#pragma unroll
    for (int off = 16; off > 0; off >>= 1) {
        sum += __shfl_xor_sync(0xFFFFFFFF, sum, off);
        sq  += __shfl_xor_sync(0xFFFFFFFF, sq,  off);
    }
    const int wid = tid >> 5, lid = tid & 31;
    if (lid == 0) { s_sum[wid] = sum; s_sq[wid] = sq; }
    __syncthreads();
    if (wid == 0) {
        float a0 = (lid < 8) ? s_sum[lid] : 0.f;
        float b0 = (lid < 8) ? s_sq[lid]  : 0.f;
#pragma unroll
        for (int off = 4; off > 0; off >>= 1) {
            a0 += __shfl_xor_sync(0xFFFFFFFF, a0, off);
            b0 += __shfl_xor_sync(0xFFFFFFFF, b0, off);
        }
        if (lid == 0) { s_sum[0] = a0; s_sq[0] = b0; }
    }
    __syncthreads();
    const float mu  = s_sum[0] * (1.f / OUT_D);
    const float var = s_sq[0] * (1.f / OUT_D) - mu * mu;
    const float inv = rsqrtf(var + LN_EPS);
#pragma unroll
    for (int l = 0; l < 2; ++l) {
        const int o = tid + l * 256;
        out[(size_t)t * OUT_D + o] = (v[l] - mu) * inv + sk[l] * (1.f - gg[l]);
    }
}

// ---------------- launch ----------------
extern "C" void kernel_launch(void* const* d_in, const int* in_sizes, int n_in,
                              void* d_out, int out_size)
{
    const float* x        = (const float*)d_in[0];
    const unsigned char* resets_raw = (const unsigned char*)d_in[1];
    const float* state_re = (const float*)d_in[2];
    const float* state_im = (const float*)d_in[3];
    const float* a        = (const float*)d_in[4];
    const float* b        = (const float*)d_in[5];
    const float* W_pre    = (const float*)d_in[6];
    const float* b_pre    = (const float*)d_in[7];
    const float* W_gi     = (const float*)d_in[8];
    const float* b_gi     = (const float*)d_in[9];
    const float* W_go     = (const float*)d_in[10];
    const float* b_go     = (const float*)d_in[11];
    const float* W_skip   = (const float*)d_in[12];
    const float* b_skip   = (const float*)d_in[13];
    const float* W_mix    = (const float*)d_in[14];
    const float* b_mix    = (const float*)d_in[15];

    // Output layout dispatch on out_size:
    //   2101248 = 4096 + 4096*512        -> final_state stored real-only (astype(f32))
    //   2105344 = 8192 + 4096*512        -> 8192 floats of state; planar [re|im]
    //   otherwise                        -> interleaved fallback
    int fs_mode;
    int seq_off;
    if (out_size == TRACE * CTX + T_STEPS * OUT_D)            { fs_mode = 0; seq_off = TRACE * CTX; }
    else if (out_size == 2 * TRACE * CTX + T_STEPS * OUT_D)   { fs_mode = 1; seq_off = 2 * TRACE * CTX; }
    else                                                      { fs_mode = 2; seq_off = 2 * TRACE * CTX; }

    float* out_f   = (float*)d_out;
    float* fs_out  = out_f;
    float* seq_out = out_f + seq_off;

    float *p_gated, *p_go, *p_skip, *p_zin, *p_zm;
    cudaGetSymbolAddress((void**)&p_gated, g_gated);
    cudaGetSymbolAddress((void**)&p_go,    g_go);
    cudaGetSymbolAddress((void**)&p_skip,  g_skip);
    cudaGetSymbolAddress((void**)&p_zin,   g_zin);
    cudaGetSymbolAddress((void**)&p_zm,    g_zm);

    normalize_resets_kernel<<<1, 256>>>(resets_raw);

    gated_kernel<<<T_STEPS / 8, 64>>>(x, W_gi, b_gi, W_pre, b_pre, p_gated);

    gemm128<<<dim3(OUT_D / 128, T_STEPS / 128), 256>>>(x, W_go,   b_go,   p_go,   T_STEPS, OUT_D, D_IN, 1);
    gemm128<<<dim3(OUT_D / 128, T_STEPS / 128), 256>>>(x, W_skip, b_skip, p_skip, T_STEPS, OUT_D, D_IN, 0);

    recurrence_kernel<<<TRACE, CTX>>>(p_gated, state_re, state_im, a, b, p_zin);
    finalize_state_kernel<<<(TRACE * CTX + 255) / 256, 256>>>(fs_out, fs_mode);

    gemm128<<<dim3(OUT_D / 128, T_STEPS / 128), 256>>>(p_zin, W_mix, b_mix, p_zm, T_STEPS, OUT_D, ZDIM, 0);

    epilogue_kernel<<<T_STEPS, 256>>>(p_zm, p_go, p_skip, seq_out);
}